// round 14
// baseline (speedup 1.0000x reference)
#include <cuda_runtime.h>
#include <cstdint>

#define S_LEN   2048
#define D_MODEL 1024
#define N_HEADS 16
#define D_HEAD  64
#define D_FF    4096

// ---------------- scratch (no allocation allowed) ----------------
__device__ float    g_ATT[S_LEN * D_MODEL];
__device__ float    g_L[N_HEADS * S_LEN];
__device__ float    g_DUMMY[S_LEN * D_MODEL];
// bf16x2 (hi/lo) packed operands for Q/K path
__device__ uint32_t g_Xh2[S_LEN * (D_MODEL / 2)];
__device__ uint32_t g_Xl2[S_LEN * (D_MODEL / 2)];
__device__ uint32_t g_WQh2[N_HEADS * D_HEAD * (D_MODEL / 2)];
__device__ uint32_t g_WQl2[N_HEADS * D_HEAD * (D_MODEL / 2)];
__device__ uint32_t g_WKh2[N_HEADS * D_HEAD * (D_MODEL / 2)];
__device__ uint32_t g_WKl2[N_HEADS * D_HEAD * (D_MODEL / 2)];
__device__ uint32_t g_Qh2[N_HEADS * S_LEN * (D_HEAD / 2)];
__device__ uint32_t g_Ql2[N_HEADS * S_LEN * (D_HEAD / 2)];
__device__ uint32_t g_Kh2[N_HEADS * S_LEN * (D_HEAD / 2)];
__device__ uint32_t g_Kl2[N_HEADS * S_LEN * (D_HEAD / 2)];
// fp16x2 packed operands
__device__ uint32_t g_Xf2[S_LEN * (D_MODEL / 2)];
__device__ uint32_t g_WVf2[D_MODEL * (D_MODEL / 2)];
__device__ uint32_t g_WOf2[D_MODEL * (D_MODEL / 2)];
__device__ uint32_t g_F1f2[D_FF * (D_MODEL / 2)];
__device__ uint32_t g_F2f2[D_MODEL * (D_FF / 2)];
__device__ uint32_t g_Vf2[N_HEADS * S_LEN * (D_HEAD / 2)];
__device__ uint32_t g_Zf2[S_LEN * (D_MODEL / 2)];
__device__ uint32_t g_ATTf2[S_LEN * (D_MODEL / 2)];
__device__ uint32_t g_HIDf2[S_LEN * (D_FF / 2)];

// =================================================================
// helpers
// =================================================================
__device__ __forceinline__ void mma16(float* c,
    uint32_t a0, uint32_t a1, uint32_t a2, uint32_t a3,
    uint32_t b0, uint32_t b1)
{
    asm volatile(
        "mma.sync.aligned.m16n8k16.row.col.f32.bf16.bf16.f32 "
        "{%0,%1,%2,%3},{%4,%5,%6,%7},{%8,%9},{%0,%1,%2,%3};"
        : "+f"(c[0]), "+f"(c[1]), "+f"(c[2]), "+f"(c[3])
        : "r"(a0), "r"(a1), "r"(a2), "r"(a3), "r"(b0), "r"(b1));
}

__device__ __forceinline__ void mma16h(float* c,
    uint32_t a0, uint32_t a1, uint32_t a2, uint32_t a3,
    uint32_t b0, uint32_t b1)
{
    asm volatile(
        "mma.sync.aligned.m16n8k16.row.col.f32.f16.f16.f32 "
        "{%0,%1,%2,%3},{%4,%5,%6,%7},{%8,%9},{%0,%1,%2,%3};"
        : "+f"(c[0]), "+f"(c[1]), "+f"(c[2]), "+f"(c[3])
        : "r"(a0), "r"(a1), "r"(a2), "r"(a3), "r"(b0), "r"(b1));
}

__device__ __forceinline__ void ldsm_x4_t(
    uint32_t& r0, uint32_t& r1, uint32_t& r2, uint32_t& r3, uint32_t addr)
{
    asm volatile(
        "ldmatrix.sync.aligned.m8n8.x4.trans.shared.b16 {%0,%1,%2,%3}, [%4];"
        : "=r"(r0), "=r"(r1), "=r"(r2), "=r"(r3) : "r"(addr));
}

__device__ __forceinline__ void pack2(float x0, float x1, uint32_t& hi, uint32_t& lo) {
    asm("cvt.rn.bf16x2.f32 %0, %1, %2;" : "=r"(hi) : "f"(x1), "f"(x0));
    float f0 = __uint_as_float(hi << 16);
    float f1 = __uint_as_float(hi & 0xffff0000u);
    asm("cvt.rn.bf16x2.f32 %0, %1, %2;" : "=r"(lo) : "f"(x1 - f1), "f"(x0 - f0));
}

__device__ __forceinline__ uint32_t packh2(float x0, float x1) {
    uint32_t r;
    asm("cvt.rn.f16x2.f32 %0, %1, %2;" : "=r"(r) : "f"(x1), "f"(x0));
    return r;
}

__device__ __forceinline__ void cp16(uint32_t dst_smem, const void* src) {
    asm volatile("cp.async.cg.shared.global [%0], [%1], 16;"
                 :: "r"(dst_smem), "l"(src));
}
#define CP_COMMIT() asm volatile("cp.async.commit_group;")
#define CP_WAIT1()  asm volatile("cp.async.wait_group 1;")
#define CP_WAIT2()  asm volatile("cp.async.wait_group 2;")

// =================================================================
// pack kernels
// =================================================================
__global__ __launch_bounds__(256) void pack_x(
    const float* __restrict__ in, uint32_t* __restrict__ oh,
    uint32_t* __restrict__ ol, uint32_t* __restrict__ of, int n4)
{
    int i = blockIdx.x * 256 + threadIdx.x;
    if (i < n4) {
        float4 v = ((const float4*)in)[i];
        uint32_t h0, l0, h1, l1;
        pack2(v.x, v.y, h0, l0);
        pack2(v.z, v.w, h1, l1);
        ((uint2*)oh)[i] = make_uint2(h0, h1);
        ((uint2*)ol)[i] = make_uint2(l0, l1);
        ((uint2*)of)[i] = make_uint2(packh2(v.x, v.y), packh2(v.z, v.w));
    }
}

__global__ __launch_bounds__(256) void pack_w2(
    const float* __restrict__ inQ, const float* __restrict__ inK,
    uint32_t* __restrict__ oQh, uint32_t* __restrict__ oQl,
    uint32_t* __restrict__ oKh, uint32_t* __restrict__ oKl)
{
    const float* in = blockIdx.y ? inK : inQ;
    uint32_t* oh = blockIdx.y ? oKh : oQh;
    uint32_t* ol = blockIdx.y ? oKl : oQl;
    int i  = blockIdx.x * 256 + threadIdx.x;
    int e  = i & 63;
    int kp = (i >> 6) & 511;
    int h  = i >> 15;
    float x0 = in[((size_t)h * 1024 + 2 * kp)     * 64 + e];
    float x1 = in[((size_t)h * 1024 + 2 * kp + 1) * 64 + e];
    uint32_t hi, lo;
    pack2(x0, x1, hi, lo);
    oh[((size_t)h * 64 + e) * 512 + kp] = hi;
    ol[((size_t)h * 64 + e) * 512 + kp] = lo;
}

__global__ __launch_bounds__(256) void pack_wf_head(
    const float* __restrict__ in, uint32_t* __restrict__ of)
{
    int i  = blockIdx.x * 256 + threadIdx.x;
    int e  = i & 63;
    int kp = (i >> 6) & 511;
    int h  = i >> 15;
    float x0 = in[((size_t)h * 1024 + 2 * kp)     * 64 + e];
    float x1 = in[((size_t)h * 1024 + 2 * kp + 1) * 64 + e];
    of[((size_t)h * 64 + e) * 512 + kp] = packh2(x0, x1);
}

__global__ __launch_bounds__(256) void pack_wf_row(
    const float* __restrict__ in, uint32_t* __restrict__ of, int npair)
{
    int i = blockIdx.x * 256 + threadIdx.x;
    if (i < npair) {
        float2 v = ((const float2*)in)[i];
        of[i] = packh2(v.x, v.y);
    }
}

// =================================================================
// Q+K projection (split-bf16, merged via blockIdx.z)
// =================================================================
#define QKP 20
#define QSTG (128 * QKP)

__global__ __launch_bounds__(256, 2) void gemm_qk(
    const uint32_t* __restrict__ Ah2g, const uint32_t* __restrict__ Al2g,
    const uint32_t* __restrict__ BQh, const uint32_t* __restrict__ BQl,
    const uint32_t* __restrict__ BKh, const uint32_t* __restrict__ BKl,
    uint32_t* __restrict__ OQh, uint32_t* __restrict__ OQl,
    uint32_t* __restrict__ OKh, uint32_t* __restrict__ OKl)
{
    extern __shared__ float sm[];
    uint32_t* smu = (uint32_t*)sm;

    const int t    = threadIdx.x;
    const int lane = t & 31;
    const int w    = t >> 5;
    const int grp  = lane >> 2;
    const int qd   = lane & 3;
    const int wm   = (w & 3) * 32;
    const int wn   = (w >> 2) * 64;
    const int m0   = blockIdx.y * 128;
    const int n0   = blockIdx.x * 128;

    const uint32_t* Bh2g = blockIdx.z ? BKh : BQh;
    const uint32_t* Bl2g = blockIdx.z ? BKl : BQl;
    uint32_t* Oh = blockIdx.z ? OKh : OQh;
    uint32_t* Ol = blockIdx.z ? OKl : OQl;

    float acc[2][8][4];
#pragma unroll
    for (int i = 0; i < 2; i++)
#pragma unroll
        for (int j = 0; j < 8; j++)
#pragma unroll
            for (int k = 0; k < 4; k++) acc[i][j][k] = 0.0f;

    const uint32_t sb = (uint32_t)__cvta_generic_to_shared(smu);

    auto issue = [&](int kt, int s) {
        const int kb = kt * 16;
        const uint32_t base = sb + (uint32_t)s * 4 * QSTG * 4;
#pragma unroll
        for (int i = t; i < 512; i += 256) {
            const int r = i >> 2, c = (i & 3) * 4;
            const uint32_t d = base + (r * QKP + c) * 4;
            cp16(d,                Ah2g + (size_t)(m0 + r) * 512 + kb + c);
            cp16(d + QSTG * 4,     Al2g + (size_t)(m0 + r) * 512 + kb + c);
            const size_t wo = (size_t)(n0 + r) * 512 + kb + c;
            cp16(d + 2 * QSTG * 4, Bh2g + wo);
            cp16(d + 3 * QSTG * 4, Bl2g + wo);
        }
    };

    issue(0, 0); CP_COMMIT();
    issue(1, 1); CP_COMMIT();

    for (int kt = 0; kt < 32; kt++) {
        CP_WAIT1();
        __syncthreads();
        const uint32_t* Ah = smu + (kt & 1) * 4 * QSTG;
        const uint32_t* Al = Ah + QSTG;
        const uint32_t* Bh = Ah + 2 * QSTG;
        const uint32_t* Bl = Ah + 3 * QSTG;

#pragma unroll
        for (int ks2 = 0; ks2 < 16; ks2 += 8) {
            uint32_t ah[2][4], al[2][4];
#pragma unroll
            for (int mt = 0; mt < 2; mt++) {
                const int r = (wm + mt * 16 + grp) * QKP;
                ah[mt][0] = Ah[r + ks2 + qd];
                ah[mt][1] = Ah[r + 8 * QKP + ks2 + qd];
                ah[mt][2] = Ah[r + ks2 + qd + 4];
                ah[mt][3] = Ah[r + 8 * QKP + ks2 + qd + 4];
                al[mt][0] = Al[r + ks2 + qd];
                al[mt][1] = Al[r + 8 * QKP + ks2 + qd];
                al[mt][2] = Al[r + ks2 + qd + 4];
                al[mt][3] = Al[r + 8 * QKP + ks2 + qd + 4];
            }
#pragma unroll
            for (int nt = 0; nt < 8; nt++) {
                const int rb = (wn + nt * 8 + grp) * QKP;
                uint32_t bh0 = Bh[rb + ks2 + qd];
                uint32_t bh1 = Bh[rb + ks2 + qd + 4];
                uint32_t bl0 = Bl[rb + ks2 + qd];
                uint32_t bl1 = Bl[rb + ks2 + qd + 4];
#pragma unroll
                for (int mt = 0; mt < 2; mt++) {
                    mma16(acc[mt][nt], ah[mt][0], ah[mt][1], ah[mt][2], ah[mt][3], bh0, bh1);
                    mma16(acc[mt][nt], ah[mt][0], ah[mt][1], ah[mt][2], ah[mt][3], bl0, bl1);
                    mma16(acc[mt][nt], al[mt][0], al[mt][1], al[mt][2], al[mt][3], bh0, bh1);
                }
            }
        }
        __syncthreads();
        if (kt + 2 < 32) issue(kt + 2, kt & 1);
        CP_COMMIT();
    }

#pragma unroll
    for (int mt = 0; mt < 2; mt++) {
#pragma unroll
        for (int nt = 0; nt < 8; nt++) {
            const int n  = n0 + wn + nt * 8 + 2 * qd;
            const int h  = n >> 6;
            const int dp = (n & 63) >> 1;
            const int mA = blockIdx.y * 128 + wm + mt * 16 + grp;
            const int mB = mA + 8;
            uint32_t hi, lo;
            pack2(acc[mt][nt][0], acc[mt][nt][1], hi, lo);
            Oh[((size_t)h * S_LEN + mA) * 32 + dp] = hi;
            Ol[((size_t)h * S_LEN + mA) * 32 + dp] = lo;
            pack2(acc[mt][nt][2], acc[mt][nt][3], hi, lo);
            Oh[((size_t)h * S_LEN + mB) * 32 + dp] = hi;
            Ol[((size_t)h * S_LEN + mB) * 32 + dp] = lo;
        }
    }
}

// =================================================================
// fp16 GEMM: operands pre-packed u32 half2 along k. moff = M-block offset.
// =================================================================
#define FP  20

template<int MT, bool BIAS, bool RELU, bool RESID, bool OUTF32, bool OUTPACK, bool OUTPACKHEAD>
__global__ __launch_bounds__(256, 2) void gemm_f16(
    const uint32_t* __restrict__ A2, const uint32_t* __restrict__ B2,
    const float* __restrict__ bias, const float* __restrict__ resid,
    float* __restrict__ Cf, uint32_t* __restrict__ Cp,
    int M, int N, int K, int moff)
{
    constexpr int ASTG = MT * FP;
    constexpr int BSTG = 128 * FP;
    constexpr int SSTG = ASTG + BSTG;
    constexpr int NTI  = (MT == 128) ? 8 : 4;

    extern __shared__ float sm[];
    uint32_t* smu = (uint32_t*)sm;

    const int t    = threadIdx.x;
    const int lane = t & 31;
    const int w    = t >> 5;
    const int grp  = lane >> 2;
    const int qd   = lane & 3;
    const int wm   = (MT == 128) ? (w & 3) * 32 : (w & 1) * 32;
    const int wn   = (MT == 128) ? (w >> 2) * 64 : (w >> 1) * 32;
    const int m0   = (blockIdx.y + moff) * MT;
    const int n0   = blockIdx.x * 128;
    const int K2   = K >> 1;
    const int KT   = K >> 5;

    float acc[2][NTI][4];
#pragma unroll
    for (int i = 0; i < 2; i++)
#pragma unroll
        for (int j = 0; j < NTI; j++)
#pragma unroll
            for (int k = 0; k < 4; k++) acc[i][j][k] = 0.0f;

    const uint32_t sb = (uint32_t)__cvta_generic_to_shared(smu);

    auto issue = [&](int kt, int s) {
        const int kb = kt * 16;
        const uint32_t base = sb + (uint32_t)s * SSTG * 4;
#pragma unroll
        for (int i = t; i < MT * 4; i += 256) {
            const int r = i >> 2, c = (i & 3) * 4;
            cp16(base + (r * FP + c) * 4, A2 + (size_t)(m0 + r) * K2 + kb + c);
        }
#pragma unroll
        for (int i = t; i < 512; i += 256) {
            const int r = i >> 2, c = (i & 3) * 4;
            cp16(base + (ASTG + r * FP + c) * 4, B2 + (size_t)(n0 + r) * K2 + kb + c);
        }
    };

    issue(0, 0); CP_COMMIT();
    issue(1, 1); CP_COMMIT();
    issue(2, 2); CP_COMMIT();

    for (int kt = 0; kt < KT; kt++) {
        const int s = kt % 3;
        CP_WAIT2();
        __syncthreads();
        const uint32_t* Ab = smu + s * SSTG;
        const uint32_t* Bb = Ab + ASTG;

#pragma unroll
        for (int ks2 = 0; ks2 < 16; ks2 += 8) {
            uint32_t af[2][4];
#pragma unroll
            for (int mt = 0; mt < 2; mt++) {
                const int r = (wm + mt * 16 + grp) * FP;
                af[mt][0] = Ab[r + ks2 + qd];
                af[mt][1] = Ab[r + 8 * FP + ks2 + qd];
                af[mt][2] = Ab[r + ks2 + qd + 4];
                af[mt][3] = Ab[r + 8 * FP + ks2 + qd + 4];
            }
#pragma unroll
            for (int nt = 0; nt < NTI; nt++) {
                const int rb = (wn + nt * 8 + grp) * FP;
                uint32_t b0 = Bb[rb + ks2 + qd];
                uint32_t b1 = Bb[rb + ks2 + qd + 4];
#pragma unroll
                for (int mt = 0; mt < 2; mt++)
                    mma16h(acc[mt][nt], af[mt][0], af[mt][1], af[mt][2], af[mt][3], b0, b1);
            }
        }
        __syncthreads();
        if (kt + 3 < KT) issue(kt + 3, s);
        CP_COMMIT();
    }

#pragma unroll
    for (int mt = 0; mt < 2; mt++) {
#pragma unroll
        for (int nt = 0; nt < NTI; nt++) {
            const int n  = n0 + wn + nt * 8 + 2 * qd;
            float2 v0 = make_float2(acc[mt][nt][0], acc[mt][nt][1]);
            float2 v1 = make_float2(acc[mt][nt][2], acc[mt][nt][3]);
            if (BIAS) {
                float2 bb = *(const float2*)&bias[n];
                v0.x += bb.x; v0.y += bb.y;
                v1.x += bb.x; v1.y += bb.y;
            }
            if (RELU) {
                v0.x = fmaxf(v0.x, 0.f); v0.y = fmaxf(v0.y, 0.f);
                v1.x = fmaxf(v1.x, 0.f); v1.y = fmaxf(v1.y, 0.f);
            }
            const int mA = m0 + wm + mt * 16 + grp;
            const int mB = mA + 8;
            if (RESID) {
                float2 r0 = *(const float2*)&resid[(size_t)mA * N + n];
                float2 r1 = *(const float2*)&resid[(size_t)mB * N + n];
                v0.x += r0.x; v0.y += r0.y;
                v1.x += r1.x; v1.y += r1.y;
            }
            if (OUTF32) {
                *(float2*)&Cf[(size_t)mA * N + n] = v0;
                *(float2*)&Cf[(size_t)mB * N + n] = v1;
            }
            if (OUTPACK) {
                Cp[(size_t)mA * (N >> 1) + (n >> 1)] = packh2(v0.x, v0.y);
                Cp[(size_t)mB * (N >> 1) + (n >> 1)] = packh2(v1.x, v1.y);
            }
            if (OUTPACKHEAD) {
                const int h  = n >> 6;
                const int dp = (n & 63) >> 1;
                Cp[((size_t)h * M + mA) * 32 + dp] = packh2(v0.x, v0.y);
                Cp[((size_t)h * M + mB) * 32 + dp] = packh2(v1.x, v1.y);
            }
        }
    }
}

// =================================================================
// Attention v3 (R12): split-bf16 scores; fp16 z with register A-frags.
// =================================================================
#define KP2 36
#define ATILE (64 * KP2)
#define ASTAGE (3 * ATILE)
#define ATTN_SMEM_U32 (2 * ATILE + 2 * ASTAGE)

__global__ __launch_bounds__(256, 2) void attn_tc(
    const uint32_t* __restrict__ Qh2, const uint32_t* __restrict__ Ql2,
    const uint32_t* __restrict__ Kh2, const uint32_t* __restrict__ Kl2,
    const uint32_t* __restrict__ Vf2g, float* __restrict__ SA,
    uint32_t* __restrict__ Zf2, float* __restrict__ Lsum)
{
    extern __shared__ float sm[];
    uint32_t* smu  = (uint32_t*)sm;
    uint32_t* Qh_s = smu;
    uint32_t* Ql_s = smu + ATILE;

    const int t    = threadIdx.x;
    const int lane = t & 31;
    const int w    = t >> 5;
    const int grp  = lane >> 2;
    const int qd   = lane & 3;
    const int wm   = (w >> 1) * 16;
    const int wn   = (w & 1) * 32;
    const int qt   = (int)gridDim.x - 1 - (int)blockIdx.x;
    const int h    = blockIdx.y;
    const int q0   = qt * 64;

    const float slope = exp2f(-0.5f * (float)(h + 1));
    const uint32_t* Qhg = Qh2 + (size_t)h * S_LEN * 32;
    const uint32_t* Qlg = Ql2 + (size_t)h * S_LEN * 32;
    const uint32_t* Khg = Kh2 + (size_t)h * S_LEN * 32;
    const uint32_t* Klg = Kl2 + (size_t)h * S_LEN * 32;
    const uint32_t* Vfg = Vf2g + (size_t)h * S_LEN * 32;

    const uint32_t sb = (uint32_t)__cvta_generic_to_shared(smu);

    auto issueif = [&](int kt) {
        if (kt <= qt) {
            const int s = kt & 1;
            const uint32_t base = sb + (uint32_t)(2 * ATILE + s * ASTAGE) * 4;
            const int k0 = kt * 64;
#pragma unroll
            for (int i = t; i < 512; i += 256) {
                const int r = i >> 3, c = (i & 7) * 4;
                const uint32_t d = base + (r * KP2 + c) * 4;
                cp16(d,                 Khg + (size_t)(k0 + r) * 32 + c);
                cp16(d + ATILE * 4,     Klg + (size_t)(k0 + r) * 32 + c);
                cp16(d + 2 * ATILE * 4, Vfg + (size_t)(k0 + r) * 32 + c);
            }
        }
        CP_COMMIT();
    };

    {
        const int r  = t >> 2;
        const int c8 = (t & 3) * 8;
        *(uint4*)&Qh_s[r * KP2 + c8]     = *(const uint4*)(Qhg + (size_t)(q0 + r) * 32 + c8);
        *(uint4*)&Qh_s[r * KP2 + c8 + 4] = *(const uint4*)(Qhg + (size_t)(q0 + r) * 32 + c8 + 4);
        *(uint4*)&Ql_s[r * KP2 + c8]     = *(const uint4*)(Qlg + (size_t)(q0 + r) * 32 + c8);
        *(uint4*)&Ql_s[r * KP2 + c8 + 4] = *(const uint4*)(Qlg + (size_t)(q0 + r) * 32 + c8 + 4);
    }

    issueif(0);
    issueif(1);

    float zacc[8][4];
#pragma unroll
    for (int i = 0; i < 8; i++)
#pragma unroll
        for (int j = 0; j < 4; j++) zacc[i][j] = 0.0f;
    float la = 0.0f, lb = 0.0f;

    const int iA = q0 + wm + grp;
    const int iB = iA + 8;

    const int lrow = (lane & 7) + ((lane >> 3) & 1) * 8;
    const int lcsh = ((lane >> 4) & 1) * 8;

    for (int kt = 0; kt <= qt; kt++) {
        const int s = kt & 1;
        const uint32_t* Kh_s = smu + 2 * ATILE + s * ASTAGE;
        const uint32_t* Kl_s = Kh_s + ATILE;
        const uint32_t  vbase = sb + (uint32_t)(2 * ATILE + s * ASTAGE + 2 * ATILE) * 4;
        const int k0 = kt * 64;

        CP_WAIT1();
        __syncthreads();

        float sacc[4][4];
#pragma unroll
        for (int i = 0; i < 4; i++)
#pragma unroll
            for (int j = 0; j < 4; j++) sacc[i][j] = 0.0f;

#pragma unroll
        for (int kp8 = 0; kp8 < 32; kp8 += 8) {
            const int rA = (wm + grp) * KP2;
            uint32_t ah0 = Qh_s[rA + kp8 + qd];
            uint32_t ah1 = Qh_s[rA + 8 * KP2 + kp8 + qd];
            uint32_t ah2 = Qh_s[rA + kp8 + qd + 4];
            uint32_t ah3 = Qh_s[rA + 8 * KP2 + kp8 + qd + 4];
            uint32_t al0 = Ql_s[rA + kp8 + qd];
            uint32_t al1 = Ql_s[rA + 8 * KP2 + kp8 + qd];
            uint32_t al2 = Ql_s[rA + kp8 + qd + 4];
            uint32_t al3 = Ql_s[rA + 8 * KP2 + kp8 + qd + 4];
#pragma unroll
            for (int nt = 0; nt < 4; nt++) {
                const int rb = (wn + nt * 8 + grp) * KP2;
                uint32_t bh0 = Kh_s[rb + kp8 + qd];
                uint32_t bh1 = Kh_s[rb + kp8 + qd + 4];
                uint32_t bl0 = Kl_s[rb + kp8 + qd];
                uint32_t bl1 = Kl_s[rb + kp8 + qd + 4];
                mma16(sacc[nt], ah0, ah1, ah2, ah3, bh0, bh1);
                mma16(sacc[nt], ah0, ah1, ah2, ah3, bl0, bl1);
                mma16(sacc[nt], al0, al1, al2, al3, bh0, bh1);
            }
        }

        const bool diag = (kt == qt);
        uint32_t pp[4], qq[4];
#pragma unroll
        for (int nt = 0; nt < 4; nt++) {
            const int j0 = k0 + wn + nt * 8 + 2 * qd;
            float p0 = __expf(sacc[nt][0] * 0.125f - (float)(iA - j0) * slope);
            float p1 = __expf(sacc[nt][1] * 0.125f - (float)(iA - j0 - 1) * slope);
            float p2 = __expf(sacc[nt][2] * 0.125f - (float)(iB - j0) * slope);
            float p3 = __expf(sacc[nt][3] * 0.125f - (float)(iB - j0 - 1) * slope);
            if (diag) {
                if (j0     > iA) p0 = 0.0f;
                if (j0 + 1 > iA) p1 = 0.0f;
                if (j0     > iB) p2 = 0.0f;
                if (j0 + 1 > iB) p3 = 0.0f;
            }
            la += p0 + p1;
            lb += p2 + p3;
            if (SA) {
                *(float2*)&SA[((size_t)h * S_LEN + iA) * S_LEN + j0] = make_float2(p0, p1);
                *(float2*)&SA[((size_t)h * S_LEN + iB) * S_LEN + j0] = make_float2(p2, p3);
            }
            pp[nt] = packh2(p0, p1);
            qq[nt] = packh2(p2, p3);
        }

#pragma unroll
        for (int ks2 = 0; ks2 < 2; ks2++) {
            uint32_t a0 = pp[2 * ks2];
            uint32_t a1 = qq[2 * ks2];
            uint32_t a2 = pp[2 * ks2 + 1];
            uint32_t a3 = qq[2 * ks2 + 1];
            const uint32_t rbase = vbase
                + (uint32_t)((wn + ks2 * 16 + lrow) * KP2) * 4;
#pragma unroll
            for (int ntp = 0; ntp < 4; ntp++) {
                uint32_t addr = rbase + (uint32_t)(ntp * 16 + lcsh) * 2;
                uint32_t b0, b1, b2, b3;
                ldsm_x4_t(b0, b1, b2, b3, addr);
                mma16h(zacc[2 * ntp],     a0, a1, a2, a3, b0, b1);
                mma16h(zacc[2 * ntp + 1], a0, a1, a2, a3, b2, b3);
            }
        }
        __syncthreads();
        issueif(kt + 2);
    }

    __syncthreads();
    float* zred = (float*)(smu + 2 * ATILE);
    if (w & 1) {
#pragma unroll
        for (int nb = 0; nb < 8; nb++) {
            const int c = nb * 8 + 2 * qd;
            *(float2*)&zred[(wm + grp)     * 66 + c] = make_float2(zacc[nb][0], zacc[nb][1]);
            *(float2*)&zred[(wm + grp + 8) * 66 + c] = make_float2(zacc[nb][2], zacc[nb][3]);
        }
    }
    __syncthreads();
    if (!(w & 1)) {
#pragma unroll
        for (int nb = 0; nb < 8; nb++) {
            const int c = nb * 8 + 2 * qd;
            float2 r0 = *(const float2*)&zred[(wm + grp)     * 66 + c];
            float2 r1 = *(const float2*)&zred[(wm + grp + 8) * 66 + c];
            zacc[nb][0] += r0.x; zacc[nb][1] += r0.y;
            zacc[nb][2] += r1.x; zacc[nb][3] += r1.y;
        }
    }

    la += __shfl_xor_sync(0xffffffffu, la, 1);
    la += __shfl_xor_sync(0xffffffffu, la, 2);
    lb += __shfl_xor_sync(0xffffffffu, lb, 1);
    lb += __shfl_xor_sync(0xffffffffu, lb, 2);
    __syncthreads();
    float* red = (float*)(smu + 2 * ATILE) + 64 * 66;
    if (qd == 0) {
        red[(w & 1) * 64 + wm + grp]     = la;
        red[(w & 1) * 64 + wm + grp + 8] = lb;
    }
    __syncthreads();
    if (!(w & 1)) {
        const float lA = red[wm + grp]     + red[64 + wm + grp];
        const float lB = red[wm + grp + 8] + red[64 + wm + grp + 8];
        if (qd == 0) {
            Lsum[h * S_LEN + iA] = lA;
            Lsum[h * S_LEN + iB] = lB;
        }
        const float liA = 1.0f / lA;
        const float liB = 1.0f / lB;
#pragma unroll
        for (int nb = 0; nb < 8; nb++) {
            const int v0 = h * D_HEAD + nb * 8 + 2 * qd;
            Zf2[(size_t)iA * (D_MODEL / 2) + (v0 >> 1)] =
                packh2(zacc[nb][0] * liA, zacc[nb][1] * liA);
            Zf2[(size_t)iB * (D_MODEL / 2) + (v0 >> 1)] =
                packh2(zacc[nb][2] * liB, zacc[nb][3] * liB);
        }
    }
}

// ---- SA upper-triangle zero-fill ----
__global__ __launch_bounds__(256) void sa_zero(float* __restrict__ SA)
{
    const int row   = blockIdx.x;
    const int i     = row & (S_LEN - 1);
    const int start = (((i >> 6) + 1) << 6) >> 2;
    float4* p = (float4*)(SA + (size_t)row * S_LEN);
    const float4 z4 = make_float4(0.f, 0.f, 0.f, 0.f);
    for (int v = start + threadIdx.x; v < S_LEN / 4; v += 256)
        p[v] = z4;
}

// ---- SA rescale: lower tiles only ----
__global__ __launch_bounds__(256) void sa_rescale(
    float* __restrict__ SA, const float* __restrict__ Lsum)
{
    const int row = blockIdx.x;
    const int i   = row & (S_LEN - 1);
    const int end = (((i >> 6) + 1) << 6) >> 2;
    const float linv = 1.0f / Lsum[row];
    float4* p = (float4*)(SA + (size_t)row * S_LEN);
    for (int v = threadIdx.x; v < end; v += 256) {
        float4 x = p[v];
        x.x *= linv; x.y *= linv; x.z *= linv; x.w *= linv;
        p[v] = x;
    }
}

// =================================================================
extern "C" void kernel_launch(void* const* d_in, const int* in_sizes, int n_in,
                              void* d_out, int out_size)
{
    const float* X   = (const float*)d_in[0];
    const float* WQ  = (const float*)d_in[1];
    const float* WK  = (const float*)d_in[2];
    const float* WV  = (const float*)d_in[3];
    const float* WOw = (const float*)d_in[4];
    const float* WOb = (const float*)d_in[5];
    const float* F1w = (const float*)d_in[6];
    const float* F1b = (const float*)d_in[7];
    const float* F2w = (const float*)d_in[8];
    const float* F2b = (const float*)d_in[9];

    float *Ap, *Lp, *Dp;
    uint32_t *Xh2, *Xl2, *WQh2, *WQl2, *WKh2, *WKl2, *Qh2, *Ql2, *Kh2, *Kl2;
    uint32_t *Xf2, *WVf2, *WOf2, *F1f2, *F2f2, *Vf2, *Zf2, *ATTf2, *HIDf2;
    cudaGetSymbolAddress((void**)&Ap, g_ATT);
    cudaGetSymbolAddress((void**)&Lp, g_L);
    cudaGetSymbolAddress((void**)&Dp, g_DUMMY);
    cudaGetSymbolAddress((void**)&Xh2, g_Xh2);
    cudaGetSymbolAddress((void**)&Xl2, g_Xl2);
    cudaGetSymbolAddress((void**)&WQh2, g_WQh2);
    cudaGetSymbolAddress((void**)&WQl2, g_WQl2);
    cudaGetSymbolAddress((void**)&WKh2, g_WKh2);
    cudaGetSymbolAddress((void**)&WKl2, g_WKl2);
    cudaGetSymbolAddress((void**)&Qh2, g_Qh2);
    cudaGetSymbolAddress((void**)&Ql2, g_Ql2);
    cudaGetSymbolAddress((void**)&Kh2, g_Kh2);
    cudaGetSymbolAddress((void**)&Kl2, g_Kl2);
    cudaGetSymbolAddress((void**)&Xf2, g_Xf2);
    cudaGetSymbolAddress((void**)&WVf2, g_WVf2);
    cudaGetSymbolAddress((void**)&WOf2, g_WOf2);
    cudaGetSymbolAddress((void**)&F1f2, g_F1f2);
    cudaGetSymbolAddress((void**)&F2f2, g_F2f2);
    cudaGetSymbolAddress((void**)&Vf2, g_Vf2);
    cudaGetSymbolAddress((void**)&Zf2, g_Zf2);
    cudaGetSymbolAddress((void**)&ATTf2, g_ATTf2);
    cudaGetSymbolAddress((void**)&HIDf2, g_HIDf2);

    const size_t SA_EL = (size_t)N_HEADS * S_LEN * S_LEN;
    const size_t OV_EL = (size_t)S_LEN * D_MODEL;
    float* out = (float*)d_out;
    float* sa;
    float* ov;
    if ((size_t)out_size >= SA_EL + OV_EL)      { sa = out;     ov = out + SA_EL; }
    else if ((size_t)out_size >= SA_EL)         { sa = out;     ov = Dp; }
    else                                        { sa = nullptr; ov = out; }

    const int attn_smem  = ATTN_SMEM_U32 * 4;
    const int qk_smem    = 8 * QSTG * 4;
    const int f16_smem   = 3 * (128 * FP + 128 * FP) * 4;
    const int f16_smem64 = 3 * (64 * FP + 128 * FP) * 4;
    cudaFuncSetAttribute(attn_tc, cudaFuncAttributeMaxDynamicSharedMemorySize, attn_smem);
    cudaFuncSetAttribute(gemm_qk, cudaFuncAttributeMaxDynamicSharedMemorySize, qk_smem);
    cudaFuncSetAttribute(gemm_f16<128,false,false,false,false,false,true >,
                         cudaFuncAttributeMaxDynamicSharedMemorySize, f16_smem);
    cudaFuncSetAttribute(gemm_f16<64 ,true ,false,true ,true ,true ,false>,
                         cudaFuncAttributeMaxDynamicSharedMemorySize, f16_smem64);
    cudaFuncSetAttribute(gemm_f16<128,true ,true ,false,false,true ,false>,
                         cudaFuncAttributeMaxDynamicSharedMemorySize, f16_smem);
    cudaFuncSetAttribute(gemm_f16<64 ,true ,false,true ,true ,false,false>,
                         cudaFuncAttributeMaxDynamicSharedMemorySize, f16_smem64);

    static cudaStream_t s2 = nullptr, s3 = nullptr;
    static cudaEvent_t evStart = nullptr, evX = nullptr, evV = nullptr,
                       evAttn = nullptr, evPack = nullptr,
                       evB = nullptr, evR = nullptr;
    if (!s2) {
        cudaStreamCreateWithFlags(&s2, cudaStreamNonBlocking);
        cudaStreamCreateWithFlags(&s3, cudaStreamNonBlocking);
        cudaEventCreateWithFlags(&evStart, cudaEventDisableTiming);
        cudaEventCreateWithFlags(&evX,     cudaEventDisableTiming);
        cudaEventCreateWithFlags(&evV,     cudaEventDisableTiming);
        cudaEventCreateWithFlags(&evAttn,  cudaEventDisableTiming);
        cudaEventCreateWithFlags(&evPack,  cudaEventDisableTiming);
        cudaEventCreateWithFlags(&evB,     cudaEventDisableTiming);
        cudaEventCreateWithFlags(&evR,     cudaEventDisableTiming);
    }

    dim3 blk(256);

    // ---- fork side streams ----
    cudaEventRecord(evStart, 0);
    cudaStreamWaitEvent(s2, evStart, 0);
    cudaStreamWaitEvent(s3, evStart, 0);

    // ---- main: pack X ----
    pack_x<<<dim3(2048), blk>>>(X, Xh2, Xl2, Xf2, S_LEN * D_MODEL / 4);
    cudaEventRecord(evX, 0);

    // ---- s2: WV pack -> V-GEMM, then SA zero + late-weight packs ----
    pack_wf_head<<<dim3(2048), blk, 0, s2>>>(WV, WVf2);
    cudaStreamWaitEvent(s2, evX, 0);
    gemm_f16<128,false,false,false,false,false,true ><<<dim3(8, 16), blk, f16_smem, s2>>>(
        Xf2, WVf2, nullptr, nullptr, nullptr, Vf2, S_LEN, D_MODEL, D_MODEL, 0);
    cudaEventRecord(evV, s2);
    if (sa)
        sa_zero<<<dim3(N_HEADS * S_LEN), blk, 0, s2>>>(sa);
    pack_wf_row<<<dim3(2048), blk, 0, s2>>>(WOw, WOf2, D_MODEL * D_MODEL / 2);
    pack_wf_row<<<dim3(8192), blk, 0, s2>>>(F1w, F1f2, D_FF * D_MODEL / 2);
    pack_wf_row<<<dim3(8192), blk, 0, s2>>>(F2w, F2f2, D_MODEL * D_FF / 2);
    cudaEventRecord(evPack, s2);

    // ---- main: merged QK pack + QK projection ----
    pack_w2<<<dim3(2048, 2), blk>>>(WQ, WK, WQh2, WQl2, WKh2, WKl2);
    gemm_qk<<<dim3(8, 16, 2), blk, qk_smem>>>(Xh2, Xl2,
        WQh2, WQl2, WKh2, WKl2, Qh2, Ql2, Kh2, Kl2);

    cudaStreamWaitEvent(0, evV, 0);
    attn_tc<<<dim3(S_LEN / 64, N_HEADS), blk, attn_smem>>>(
        Qh2, Ql2, Kh2, Kl2, Vf2, sa, Zf2, Lp);
    cudaEventRecord(evAttn, 0);

    // ---- s3: SA rescale, fully concurrent with the tail GEMMs ----
    if (sa) {
        cudaStreamWaitEvent(s3, evAttn, 0);
        sa_rescale<<<dim3(N_HEADS * S_LEN), blk, 0, s3>>>(sa, Lp);
        cudaEventRecord(evR, s3);
    }

    // ---- tail pipeline: M split in halves across main(A) and s2(B) ----
    cudaStreamWaitEvent(0, evPack, 0);
    cudaStreamWaitEvent(s2, evAttn, 0);   // s2 already ordered after evPack

    // WO: ATT = X + Z @ WO^T + b   (MT=64; halves 16+16 y-blocks)
    gemm_f16<64 ,true ,false,true ,true ,true ,false><<<dim3(8, 16), blk, f16_smem64>>>(
        Zf2, WOf2, WOb, X, Ap, ATTf2, S_LEN, D_MODEL, D_MODEL, 0);
    gemm_f16<64 ,true ,false,true ,true ,true ,false><<<dim3(8, 16), blk, f16_smem64, s2>>>(
        Zf2, WOf2, WOb, X, Ap, ATTf2, S_LEN, D_MODEL, D_MODEL, 16);

    // FF1: HID = relu(ATT @ FF1^T + b1)   (MT=128; halves 8+8 y-blocks)
    gemm_f16<128,true ,true ,false,false,true ,false><<<dim3(32, 8), blk, f16_smem>>>(
        ATTf2, F1f2, F1b, nullptr, nullptr, HIDf2, S_LEN, D_FF, D_MODEL, 0);
    gemm_f16<128,true ,true ,false,false,true ,false><<<dim3(32, 8), blk, f16_smem, s2>>>(
        ATTf2, F1f2, F1b, nullptr, nullptr, HIDf2, S_LEN, D_FF, D_MODEL, 8);

    // FF2: out = ATT + HID @ FF2^T + b2   (MT=64; halves 16+16 y-blocks)
    gemm_f16<64 ,true ,false,true ,true ,false,false><<<dim3(8, 16), blk, f16_smem64>>>(
        HIDf2, F2f2, F2b, Ap, ov, nullptr, S_LEN, D_MODEL, D_FF, 0);
    gemm_f16<64 ,true ,false,true ,true ,false,false><<<dim3(8, 16), blk, f16_smem64, s2>>>(
        HIDf2, F2f2, F2b, Ap, ov, nullptr, S_LEN, D_MODEL, D_FF, 16);
    cudaEventRecord(evB, s2);

    // ---- join ----
    cudaStreamWaitEvent(0, evB, 0);
    if (sa)
        cudaStreamWaitEvent(0, evR, 0);
}

// round 15
// speedup vs baseline: 1.0223x; 1.0223x over previous
#include <cuda_runtime.h>
#include <cstdint>

#define S_LEN   2048
#define D_MODEL 1024
#define N_HEADS 16
#define D_HEAD  64
#define D_FF    4096

// ---------------- scratch (no allocation allowed) ----------------
__device__ float    g_ATT[S_LEN * D_MODEL];
__device__ float    g_L[N_HEADS * S_LEN];
__device__ float    g_DUMMY[S_LEN * D_MODEL];
// bf16x2 (hi/lo) packed operands for Q/K path
__device__ uint32_t g_Xh2[S_LEN * (D_MODEL / 2)];
__device__ uint32_t g_Xl2[S_LEN * (D_MODEL / 2)];
__device__ uint32_t g_WQh2[N_HEADS * D_HEAD * (D_MODEL / 2)];
__device__ uint32_t g_WQl2[N_HEADS * D_HEAD * (D_MODEL / 2)];
__device__ uint32_t g_WKh2[N_HEADS * D_HEAD * (D_MODEL / 2)];
__device__ uint32_t g_WKl2[N_HEADS * D_HEAD * (D_MODEL / 2)];
__device__ uint32_t g_Qh2[N_HEADS * S_LEN * (D_HEAD / 2)];
__device__ uint32_t g_Ql2[N_HEADS * S_LEN * (D_HEAD / 2)];
__device__ uint32_t g_Kh2[N_HEADS * S_LEN * (D_HEAD / 2)];
__device__ uint32_t g_Kl2[N_HEADS * S_LEN * (D_HEAD / 2)];
// fp16x2 packed operands
__device__ uint32_t g_Xf2[S_LEN * (D_MODEL / 2)];
__device__ uint32_t g_WVf2[D_MODEL * (D_MODEL / 2)];
__device__ uint32_t g_WOf2[D_MODEL * (D_MODEL / 2)];
__device__ uint32_t g_F1f2[D_FF * (D_MODEL / 2)];
__device__ uint32_t g_F2f2[D_MODEL * (D_FF / 2)];
__device__ uint32_t g_Vf2[N_HEADS * S_LEN * (D_HEAD / 2)];
__device__ uint32_t g_Zf2[S_LEN * (D_MODEL / 2)];
__device__ uint32_t g_ATTf2[S_LEN * (D_MODEL / 2)];
__device__ uint32_t g_HIDf2[S_LEN * (D_FF / 2)];

// =================================================================
// helpers
// =================================================================
__device__ __forceinline__ void mma16(float* c,
    uint32_t a0, uint32_t a1, uint32_t a2, uint32_t a3,
    uint32_t b0, uint32_t b1)
{
    asm volatile(
        "mma.sync.aligned.m16n8k16.row.col.f32.bf16.bf16.f32 "
        "{%0,%1,%2,%3},{%4,%5,%6,%7},{%8,%9},{%0,%1,%2,%3};"
        : "+f"(c[0]), "+f"(c[1]), "+f"(c[2]), "+f"(c[3])
        : "r"(a0), "r"(a1), "r"(a2), "r"(a3), "r"(b0), "r"(b1));
}

__device__ __forceinline__ void mma16h(float* c,
    uint32_t a0, uint32_t a1, uint32_t a2, uint32_t a3,
    uint32_t b0, uint32_t b1)
{
    asm volatile(
        "mma.sync.aligned.m16n8k16.row.col.f32.f16.f16.f32 "
        "{%0,%1,%2,%3},{%4,%5,%6,%7},{%8,%9},{%0,%1,%2,%3};"
        : "+f"(c[0]), "+f"(c[1]), "+f"(c[2]), "+f"(c[3])
        : "r"(a0), "r"(a1), "r"(a2), "r"(a3), "r"(b0), "r"(b1));
}

__device__ __forceinline__ void ldsm_x4_t(
    uint32_t& r0, uint32_t& r1, uint32_t& r2, uint32_t& r3, uint32_t addr)
{
    asm volatile(
        "ldmatrix.sync.aligned.m8n8.x4.trans.shared.b16 {%0,%1,%2,%3}, [%4];"
        : "=r"(r0), "=r"(r1), "=r"(r2), "=r"(r3) : "r"(addr));
}

__device__ __forceinline__ void pack2(float x0, float x1, uint32_t& hi, uint32_t& lo) {
    asm("cvt.rn.bf16x2.f32 %0, %1, %2;" : "=r"(hi) : "f"(x1), "f"(x0));
    float f0 = __uint_as_float(hi << 16);
    float f1 = __uint_as_float(hi & 0xffff0000u);
    asm("cvt.rn.bf16x2.f32 %0, %1, %2;" : "=r"(lo) : "f"(x1 - f1), "f"(x0 - f0));
}

__device__ __forceinline__ uint32_t packh2(float x0, float x1) {
    uint32_t r;
    asm("cvt.rn.f16x2.f32 %0, %1, %2;" : "=r"(r) : "f"(x1), "f"(x0));
    return r;
}

__device__ __forceinline__ void cp16(uint32_t dst_smem, const void* src) {
    asm volatile("cp.async.cg.shared.global [%0], [%1], 16;"
                 :: "r"(dst_smem), "l"(src));
}
#define CP_COMMIT() asm volatile("cp.async.commit_group;")
#define CP_WAIT1()  asm volatile("cp.async.wait_group 1;")
#define CP_WAIT2()  asm volatile("cp.async.wait_group 2;")

// =================================================================
// pack kernels
// =================================================================
__global__ __launch_bounds__(256) void pack_x(
    const float* __restrict__ in, uint32_t* __restrict__ oh,
    uint32_t* __restrict__ ol, uint32_t* __restrict__ of, int n4)
{
    int i = blockIdx.x * 256 + threadIdx.x;
    if (i < n4) {
        float4 v = ((const float4*)in)[i];
        uint32_t h0, l0, h1, l1;
        pack2(v.x, v.y, h0, l0);
        pack2(v.z, v.w, h1, l1);
        ((uint2*)oh)[i] = make_uint2(h0, h1);
        ((uint2*)ol)[i] = make_uint2(l0, l1);
        ((uint2*)of)[i] = make_uint2(packh2(v.x, v.y), packh2(v.z, v.w));
    }
}

__global__ __launch_bounds__(256) void pack_w2(
    const float* __restrict__ inQ, const float* __restrict__ inK,
    uint32_t* __restrict__ oQh, uint32_t* __restrict__ oQl,
    uint32_t* __restrict__ oKh, uint32_t* __restrict__ oKl)
{
    const float* in = blockIdx.y ? inK : inQ;
    uint32_t* oh = blockIdx.y ? oKh : oQh;
    uint32_t* ol = blockIdx.y ? oKl : oQl;
    int i  = blockIdx.x * 256 + threadIdx.x;
    int e  = i & 63;
    int kp = (i >> 6) & 511;
    int h  = i >> 15;
    float x0 = in[((size_t)h * 1024 + 2 * kp)     * 64 + e];
    float x1 = in[((size_t)h * 1024 + 2 * kp + 1) * 64 + e];
    uint32_t hi, lo;
    pack2(x0, x1, hi, lo);
    oh[((size_t)h * 64 + e) * 512 + kp] = hi;
    ol[((size_t)h * 64 + e) * 512 + kp] = lo;
}

__global__ __launch_bounds__(256) void pack_wf_head(
    const float* __restrict__ in, uint32_t* __restrict__ of)
{
    int i  = blockIdx.x * 256 + threadIdx.x;
    int e  = i & 63;
    int kp = (i >> 6) & 511;
    int h  = i >> 15;
    float x0 = in[((size_t)h * 1024 + 2 * kp)     * 64 + e];
    float x1 = in[((size_t)h * 1024 + 2 * kp + 1) * 64 + e];
    of[((size_t)h * 64 + e) * 512 + kp] = packh2(x0, x1);
}

__global__ __launch_bounds__(256) void pack_wf_row(
    const float* __restrict__ in, uint32_t* __restrict__ of, int npair)
{
    int i = blockIdx.x * 256 + threadIdx.x;
    if (i < npair) {
        float2 v = ((const float2*)in)[i];
        of[i] = packh2(v.x, v.y);
    }
}

// =================================================================
// Q+K projection (split-bf16, merged via blockIdx.z)
// =================================================================
#define QKP 20
#define QSTG (128 * QKP)

__global__ __launch_bounds__(256, 2) void gemm_qk(
    const uint32_t* __restrict__ Ah2g, const uint32_t* __restrict__ Al2g,
    const uint32_t* __restrict__ BQh, const uint32_t* __restrict__ BQl,
    const uint32_t* __restrict__ BKh, const uint32_t* __restrict__ BKl,
    uint32_t* __restrict__ OQh, uint32_t* __restrict__ OQl,
    uint32_t* __restrict__ OKh, uint32_t* __restrict__ OKl)
{
    extern __shared__ float sm[];
    uint32_t* smu = (uint32_t*)sm;

    const int t    = threadIdx.x;
    const int lane = t & 31;
    const int w    = t >> 5;
    const int grp  = lane >> 2;
    const int qd   = lane & 3;
    const int wm   = (w & 3) * 32;
    const int wn   = (w >> 2) * 64;
    const int m0   = blockIdx.y * 128;
    const int n0   = blockIdx.x * 128;

    const uint32_t* Bh2g = blockIdx.z ? BKh : BQh;
    const uint32_t* Bl2g = blockIdx.z ? BKl : BQl;
    uint32_t* Oh = blockIdx.z ? OKh : OQh;
    uint32_t* Ol = blockIdx.z ? OKl : OQl;

    float acc[2][8][4];
#pragma unroll
    for (int i = 0; i < 2; i++)
#pragma unroll
        for (int j = 0; j < 8; j++)
#pragma unroll
            for (int k = 0; k < 4; k++) acc[i][j][k] = 0.0f;

    const uint32_t sb = (uint32_t)__cvta_generic_to_shared(smu);

    auto issue = [&](int kt, int s) {
        const int kb = kt * 16;
        const uint32_t base = sb + (uint32_t)s * 4 * QSTG * 4;
#pragma unroll
        for (int i = t; i < 512; i += 256) {
            const int r = i >> 2, c = (i & 3) * 4;
            const uint32_t d = base + (r * QKP + c) * 4;
            cp16(d,                Ah2g + (size_t)(m0 + r) * 512 + kb + c);
            cp16(d + QSTG * 4,     Al2g + (size_t)(m0 + r) * 512 + kb + c);
            const size_t wo = (size_t)(n0 + r) * 512 + kb + c;
            cp16(d + 2 * QSTG * 4, Bh2g + wo);
            cp16(d + 3 * QSTG * 4, Bl2g + wo);
        }
    };

    issue(0, 0); CP_COMMIT();
    issue(1, 1); CP_COMMIT();

    for (int kt = 0; kt < 32; kt++) {
        CP_WAIT1();
        __syncthreads();
        const uint32_t* Ah = smu + (kt & 1) * 4 * QSTG;
        const uint32_t* Al = Ah + QSTG;
        const uint32_t* Bh = Ah + 2 * QSTG;
        const uint32_t* Bl = Ah + 3 * QSTG;

#pragma unroll
        for (int ks2 = 0; ks2 < 16; ks2 += 8) {
            uint32_t ah[2][4], al[2][4];
#pragma unroll
            for (int mt = 0; mt < 2; mt++) {
                const int r = (wm + mt * 16 + grp) * QKP;
                ah[mt][0] = Ah[r + ks2 + qd];
                ah[mt][1] = Ah[r + 8 * QKP + ks2 + qd];
                ah[mt][2] = Ah[r + ks2 + qd + 4];
                ah[mt][3] = Ah[r + 8 * QKP + ks2 + qd + 4];
                al[mt][0] = Al[r + ks2 + qd];
                al[mt][1] = Al[r + 8 * QKP + ks2 + qd];
                al[mt][2] = Al[r + ks2 + qd + 4];
                al[mt][3] = Al[r + 8 * QKP + ks2 + qd + 4];
            }
#pragma unroll
            for (int nt = 0; nt < 8; nt++) {
                const int rb = (wn + nt * 8 + grp) * QKP;
                uint32_t bh0 = Bh[rb + ks2 + qd];
                uint32_t bh1 = Bh[rb + ks2 + qd + 4];
                uint32_t bl0 = Bl[rb + ks2 + qd];
                uint32_t bl1 = Bl[rb + ks2 + qd + 4];
#pragma unroll
                for (int mt = 0; mt < 2; mt++) {
                    mma16(acc[mt][nt], ah[mt][0], ah[mt][1], ah[mt][2], ah[mt][3], bh0, bh1);
                    mma16(acc[mt][nt], ah[mt][0], ah[mt][1], ah[mt][2], ah[mt][3], bl0, bl1);
                    mma16(acc[mt][nt], al[mt][0], al[mt][1], al[mt][2], al[mt][3], bh0, bh1);
                }
            }
        }
        __syncthreads();
        if (kt + 2 < 32) issue(kt + 2, kt & 1);
        CP_COMMIT();
    }

#pragma unroll
    for (int mt = 0; mt < 2; mt++) {
#pragma unroll
        for (int nt = 0; nt < 8; nt++) {
            const int n  = n0 + wn + nt * 8 + 2 * qd;
            const int h  = n >> 6;
            const int dp = (n & 63) >> 1;
            const int mA = blockIdx.y * 128 + wm + mt * 16 + grp;
            const int mB = mA + 8;
            uint32_t hi, lo;
            pack2(acc[mt][nt][0], acc[mt][nt][1], hi, lo);
            Oh[((size_t)h * S_LEN + mA) * 32 + dp] = hi;
            Ol[((size_t)h * S_LEN + mA) * 32 + dp] = lo;
            pack2(acc[mt][nt][2], acc[mt][nt][3], hi, lo);
            Oh[((size_t)h * S_LEN + mB) * 32 + dp] = hi;
            Ol[((size_t)h * S_LEN + mB) * 32 + dp] = lo;
        }
    }
}

// =================================================================
// fp16 GEMM: operands pre-packed u32 half2 along k.
// =================================================================
#define FP  20

template<int MT, bool BIAS, bool RELU, bool RESID, bool OUTF32, bool OUTPACK, bool OUTPACKHEAD>
__global__ __launch_bounds__(256, 2) void gemm_f16(
    const uint32_t* __restrict__ A2, const uint32_t* __restrict__ B2,
    const float* __restrict__ bias, const float* __restrict__ resid,
    float* __restrict__ Cf, uint32_t* __restrict__ Cp,
    int M, int N, int K)
{
    constexpr int ASTG = MT * FP;
    constexpr int BSTG = 128 * FP;
    constexpr int SSTG = ASTG + BSTG;
    constexpr int NTI  = (MT == 128) ? 8 : 4;

    extern __shared__ float sm[];
    uint32_t* smu = (uint32_t*)sm;

    const int t    = threadIdx.x;
    const int lane = t & 31;
    const int w    = t >> 5;
    const int grp  = lane >> 2;
    const int qd   = lane & 3;
    const int wm   = (MT == 128) ? (w & 3) * 32 : (w & 1) * 32;
    const int wn   = (MT == 128) ? (w >> 2) * 64 : (w >> 1) * 32;
    const int m0   = blockIdx.y * MT;
    const int n0   = blockIdx.x * 128;
    const int K2   = K >> 1;
    const int KT   = K >> 5;

    float acc[2][NTI][4];
#pragma unroll
    for (int i = 0; i < 2; i++)
#pragma unroll
        for (int j = 0; j < NTI; j++)
#pragma unroll
            for (int k = 0; k < 4; k++) acc[i][j][k] = 0.0f;

    const uint32_t sb = (uint32_t)__cvta_generic_to_shared(smu);

    auto issue = [&](int kt, int s) {
        const int kb = kt * 16;
        const uint32_t base = sb + (uint32_t)s * SSTG * 4;
#pragma unroll
        for (int i = t; i < MT * 4; i += 256) {
            const int r = i >> 2, c = (i & 3) * 4;
            cp16(base + (r * FP + c) * 4, A2 + (size_t)(m0 + r) * K2 + kb + c);
        }
#pragma unroll
        for (int i = t; i < 512; i += 256) {
            const int r = i >> 2, c = (i & 3) * 4;
            cp16(base + (ASTG + r * FP + c) * 4, B2 + (size_t)(n0 + r) * K2 + kb + c);
        }
    };

    issue(0, 0); CP_COMMIT();
    issue(1, 1); CP_COMMIT();
    issue(2, 2); CP_COMMIT();

    for (int kt = 0; kt < KT; kt++) {
        const int s = kt % 3;
        CP_WAIT2();
        __syncthreads();
        const uint32_t* Ab = smu + s * SSTG;
        const uint32_t* Bb = Ab + ASTG;

#pragma unroll
        for (int ks2 = 0; ks2 < 16; ks2 += 8) {
            uint32_t af[2][4];
#pragma unroll
            for (int mt = 0; mt < 2; mt++) {
                const int r = (wm + mt * 16 + grp) * FP;
                af[mt][0] = Ab[r + ks2 + qd];
                af[mt][1] = Ab[r + 8 * FP + ks2 + qd];
                af[mt][2] = Ab[r + ks2 + qd + 4];
                af[mt][3] = Ab[r + 8 * FP + ks2 + qd + 4];
            }
#pragma unroll
            for (int nt = 0; nt < NTI; nt++) {
                const int rb = (wn + nt * 8 + grp) * FP;
                uint32_t b0 = Bb[rb + ks2 + qd];
                uint32_t b1 = Bb[rb + ks2 + qd + 4];
#pragma unroll
                for (int mt = 0; mt < 2; mt++)
                    mma16h(acc[mt][nt], af[mt][0], af[mt][1], af[mt][2], af[mt][3], b0, b1);
            }
        }
        __syncthreads();
        if (kt + 3 < KT) issue(kt + 3, s);
        CP_COMMIT();
    }

#pragma unroll
    for (int mt = 0; mt < 2; mt++) {
#pragma unroll
        for (int nt = 0; nt < NTI; nt++) {
            const int n  = n0 + wn + nt * 8 + 2 * qd;
            float2 v0 = make_float2(acc[mt][nt][0], acc[mt][nt][1]);
            float2 v1 = make_float2(acc[mt][nt][2], acc[mt][nt][3]);
            if (BIAS) {
                float2 bb = *(const float2*)&bias[n];
                v0.x += bb.x; v0.y += bb.y;
                v1.x += bb.x; v1.y += bb.y;
            }
            if (RELU) {
                v0.x = fmaxf(v0.x, 0.f); v0.y = fmaxf(v0.y, 0.f);
                v1.x = fmaxf(v1.x, 0.f); v1.y = fmaxf(v1.y, 0.f);
            }
            const int mA = m0 + wm + mt * 16 + grp;
            const int mB = mA + 8;
            if (RESID) {
                float2 r0 = *(const float2*)&resid[(size_t)mA * N + n];
                float2 r1 = *(const float2*)&resid[(size_t)mB * N + n];
                v0.x += r0.x; v0.y += r0.y;
                v1.x += r1.x; v1.y += r1.y;
            }
            if (OUTF32) {
                *(float2*)&Cf[(size_t)mA * N + n] = v0;
                *(float2*)&Cf[(size_t)mB * N + n] = v1;
            }
            if (OUTPACK) {
                Cp[(size_t)mA * (N >> 1) + (n >> 1)] = packh2(v0.x, v0.y);
                Cp[(size_t)mB * (N >> 1) + (n >> 1)] = packh2(v1.x, v1.y);
            }
            if (OUTPACKHEAD) {
                const int h  = n >> 6;
                const int dp = (n & 63) >> 1;
                Cp[((size_t)h * M + mA) * 32 + dp] = packh2(v0.x, v0.y);
                Cp[((size_t)h * M + mB) * 32 + dp] = packh2(v1.x, v1.y);
            }
        }
    }
}

// =================================================================
// Attention: split-bf16 scores; fp16 z with register A-frags.
// 3 CTAs/SM (smem 73728*3 = 221184 <= 228KB) for latency hiding.
// =================================================================
#define KP2 36
#define ATILE (64 * KP2)
#define ASTAGE (3 * ATILE)
#define ATTN_SMEM_U32 (2 * ATILE + 2 * ASTAGE)

__global__ __launch_bounds__(256, 3) void attn_tc(
    const uint32_t* __restrict__ Qh2, const uint32_t* __restrict__ Ql2,
    const uint32_t* __restrict__ Kh2, const uint32_t* __restrict__ Kl2,
    const uint32_t* __restrict__ Vf2g, float* __restrict__ SA,
    uint32_t* __restrict__ Zf2, float* __restrict__ Lsum)
{
    extern __shared__ float sm[];
    uint32_t* smu  = (uint32_t*)sm;
    uint32_t* Qh_s = smu;
    uint32_t* Ql_s = smu + ATILE;

    const int t    = threadIdx.x;
    const int lane = t & 31;
    const int w    = t >> 5;
    const int grp  = lane >> 2;
    const int qd   = lane & 3;
    const int wm   = (w >> 1) * 16;
    const int wn   = (w & 1) * 32;
    const int qt   = (int)gridDim.x - 1 - (int)blockIdx.x;
    const int h    = blockIdx.y;
    const int q0   = qt * 64;

    const float slope = exp2f(-0.5f * (float)(h + 1));
    const uint32_t* Qhg = Qh2 + (size_t)h * S_LEN * 32;
    const uint32_t* Qlg = Ql2 + (size_t)h * S_LEN * 32;
    const uint32_t* Khg = Kh2 + (size_t)h * S_LEN * 32;
    const uint32_t* Klg = Kl2 + (size_t)h * S_LEN * 32;
    const uint32_t* Vfg = Vf2g + (size_t)h * S_LEN * 32;

    const uint32_t sb = (uint32_t)__cvta_generic_to_shared(smu);

    auto issueif = [&](int kt) {
        if (kt <= qt) {
            const int s = kt & 1;
            const uint32_t base = sb + (uint32_t)(2 * ATILE + s * ASTAGE) * 4;
            const int k0 = kt * 64;
#pragma unroll
            for (int i = t; i < 512; i += 256) {
                const int r = i >> 3, c = (i & 7) * 4;
                const uint32_t d = base + (r * KP2 + c) * 4;
                cp16(d,                 Khg + (size_t)(k0 + r) * 32 + c);
                cp16(d + ATILE * 4,     Klg + (size_t)(k0 + r) * 32 + c);
                cp16(d + 2 * ATILE * 4, Vfg + (size_t)(k0 + r) * 32 + c);
            }
        }
        CP_COMMIT();
    };

    {
        const int r  = t >> 2;
        const int c8 = (t & 3) * 8;
        *(uint4*)&Qh_s[r * KP2 + c8]     = *(const uint4*)(Qhg + (size_t)(q0 + r) * 32 + c8);
        *(uint4*)&Qh_s[r * KP2 + c8 + 4] = *(const uint4*)(Qhg + (size_t)(q0 + r) * 32 + c8 + 4);
        *(uint4*)&Ql_s[r * KP2 + c8]     = *(const uint4*)(Qlg + (size_t)(q0 + r) * 32 + c8);
        *(uint4*)&Ql_s[r * KP2 + c8 + 4] = *(const uint4*)(Qlg + (size_t)(q0 + r) * 32 + c8 + 4);
    }

    issueif(0);
    issueif(1);

    float zacc[8][4];
#pragma unroll
    for (int i = 0; i < 8; i++)
#pragma unroll
        for (int j = 0; j < 4; j++) zacc[i][j] = 0.0f;
    float la = 0.0f, lb = 0.0f;

    const int iA = q0 + wm + grp;
    const int iB = iA + 8;

    const int lrow = (lane & 7) + ((lane >> 3) & 1) * 8;
    const int lcsh = ((lane >> 4) & 1) * 8;

    for (int kt = 0; kt <= qt; kt++) {
        const int s = kt & 1;
        const uint32_t* Kh_s = smu + 2 * ATILE + s * ASTAGE;
        const uint32_t* Kl_s = Kh_s + ATILE;
        const uint32_t  vbase = sb + (uint32_t)(2 * ATILE + s * ASTAGE + 2 * ATILE) * 4;
        const int k0 = kt * 64;

        CP_WAIT1();
        __syncthreads();

        float sacc[4][4];
#pragma unroll
        for (int i = 0; i < 4; i++)
#pragma unroll
            for (int j = 0; j < 4; j++) sacc[i][j] = 0.0f;

#pragma unroll
        for (int kp8 = 0; kp8 < 32; kp8 += 8) {
            const int rA = (wm + grp) * KP2;
            uint32_t ah0 = Qh_s[rA + kp8 + qd];
            uint32_t ah1 = Qh_s[rA + 8 * KP2 + kp8 + qd];
            uint32_t ah2 = Qh_s[rA + kp8 + qd + 4];
            uint32_t ah3 = Qh_s[rA + 8 * KP2 + kp8 + qd + 4];
            uint32_t al0 = Ql_s[rA + kp8 + qd];
            uint32_t al1 = Ql_s[rA + 8 * KP2 + kp8 + qd];
            uint32_t al2 = Ql_s[rA + kp8 + qd + 4];
            uint32_t al3 = Ql_s[rA + 8 * KP2 + kp8 + qd + 4];
#pragma unroll
            for (int nt = 0; nt < 4; nt++) {
                const int rb = (wn + nt * 8 + grp) * KP2;
                uint32_t bh0 = Kh_s[rb + kp8 + qd];
                uint32_t bh1 = Kh_s[rb + kp8 + qd + 4];
                uint32_t bl0 = Kl_s[rb + kp8 + qd];
                uint32_t bl1 = Kl_s[rb + kp8 + qd + 4];
                mma16(sacc[nt], ah0, ah1, ah2, ah3, bh0, bh1);
                mma16(sacc[nt], ah0, ah1, ah2, ah3, bl0, bl1);
                mma16(sacc[nt], al0, al1, al2, al3, bh0, bh1);
            }
        }

        const bool diag = (kt == qt);
        uint32_t pp[4], qq[4];
#pragma unroll
        for (int nt = 0; nt < 4; nt++) {
            const int j0 = k0 + wn + nt * 8 + 2 * qd;
            float p0 = __expf(sacc[nt][0] * 0.125f - (float)(iA - j0) * slope);
            float p1 = __expf(sacc[nt][1] * 0.125f - (float)(iA - j0 - 1) * slope);
            float p2 = __expf(sacc[nt][2] * 0.125f - (float)(iB - j0) * slope);
            float p3 = __expf(sacc[nt][3] * 0.125f - (float)(iB - j0 - 1) * slope);
            if (diag) {
                if (j0     > iA) p0 = 0.0f;
                if (j0 + 1 > iA) p1 = 0.0f;
                if (j0     > iB) p2 = 0.0f;
                if (j0 + 1 > iB) p3 = 0.0f;
            }
            la += p0 + p1;
            lb += p2 + p3;
            if (SA) {
                *(float2*)&SA[((size_t)h * S_LEN + iA) * S_LEN + j0] = make_float2(p0, p1);
                *(float2*)&SA[((size_t)h * S_LEN + iB) * S_LEN + j0] = make_float2(p2, p3);
            }
            pp[nt] = packh2(p0, p1);
            qq[nt] = packh2(p2, p3);
        }

#pragma unroll
        for (int ks2 = 0; ks2 < 2; ks2++) {
            uint32_t a0 = pp[2 * ks2];
            uint32_t a1 = qq[2 * ks2];
            uint32_t a2 = pp[2 * ks2 + 1];
            uint32_t a3 = qq[2 * ks2 + 1];
            const uint32_t rbase = vbase
                + (uint32_t)((wn + ks2 * 16 + lrow) * KP2) * 4;
#pragma unroll
            for (int ntp = 0; ntp < 4; ntp++) {
                uint32_t addr = rbase + (uint32_t)(ntp * 16 + lcsh) * 2;
                uint32_t b0, b1, b2, b3;
                ldsm_x4_t(b0, b1, b2, b3, addr);
                mma16h(zacc[2 * ntp],     a0, a1, a2, a3, b0, b1);
                mma16h(zacc[2 * ntp + 1], a0, a1, a2, a3, b2, b3);
            }
        }
        __syncthreads();
        issueif(kt + 2);
    }

    __syncthreads();
    float* zred = (float*)(smu + 2 * ATILE);
    if (w & 1) {
#pragma unroll
        for (int nb = 0; nb < 8; nb++) {
            const int c = nb * 8 + 2 * qd;
            *(float2*)&zred[(wm + grp)     * 66 + c] = make_float2(zacc[nb][0], zacc[nb][1]);
            *(float2*)&zred[(wm + grp + 8) * 66 + c] = make_float2(zacc[nb][2], zacc[nb][3]);
        }
    }
    __syncthreads();
    if (!(w & 1)) {
#pragma unroll
        for (int nb = 0; nb < 8; nb++) {
            const int c = nb * 8 + 2 * qd;
            float2 r0 = *(const float2*)&zred[(wm + grp)     * 66 + c];
            float2 r1 = *(const float2*)&zred[(wm + grp + 8) * 66 + c];
            zacc[nb][0] += r0.x; zacc[nb][1] += r0.y;
            zacc[nb][2] += r1.x; zacc[nb][3] += r1.y;
        }
    }

    la += __shfl_xor_sync(0xffffffffu, la, 1);
    la += __shfl_xor_sync(0xffffffffu, la, 2);
    lb += __shfl_xor_sync(0xffffffffu, lb, 1);
    lb += __shfl_xor_sync(0xffffffffu, lb, 2);
    __syncthreads();
    float* red = (float*)(smu + 2 * ATILE) + 64 * 66;
    if (qd == 0) {
        red[(w & 1) * 64 + wm + grp]     = la;
        red[(w & 1) * 64 + wm + grp + 8] = lb;
    }
    __syncthreads();
    if (!(w & 1)) {
        const float lA = red[wm + grp]     + red[64 + wm + grp];
        const float lB = red[wm + grp + 8] + red[64 + wm + grp + 8];
        if (qd == 0) {
            Lsum[h * S_LEN + iA] = lA;
            Lsum[h * S_LEN + iB] = lB;
        }
        const float liA = 1.0f / lA;
        const float liB = 1.0f / lB;
#pragma unroll
        for (int nb = 0; nb < 8; nb++) {
            const int v0 = h * D_HEAD + nb * 8 + 2 * qd;
            Zf2[(size_t)iA * (D_MODEL / 2) + (v0 >> 1)] =
                packh2(zacc[nb][0] * liA, zacc[nb][1] * liA);
            Zf2[(size_t)iB * (D_MODEL / 2) + (v0 >> 1)] =
                packh2(zacc[nb][2] * liB, zacc[nb][3] * liB);
        }
    }
}

// ---- SA upper-triangle zero-fill ----
__global__ __launch_bounds__(256) void sa_zero(float* __restrict__ SA)
{
    const int row   = blockIdx.x;
    const int i     = row & (S_LEN - 1);
    const int start = (((i >> 6) + 1) << 6) >> 2;
    float4* p = (float4*)(SA + (size_t)row * S_LEN);
    const float4 z4 = make_float4(0.f, 0.f, 0.f, 0.f);
    for (int v = start + threadIdx.x; v < S_LEN / 4; v += 256)
        p[v] = z4;
}

// ---- SA rescale: lower tiles only ----
__global__ __launch_bounds__(256) void sa_rescale(
    float* __restrict__ SA, const float* __restrict__ Lsum)
{
    const int row = blockIdx.x;
    const int i   = row & (S_LEN - 1);
    const int end = (((i >> 6) + 1) << 6) >> 2;
    const float linv = 1.0f / Lsum[row];
    float4* p = (float4*)(SA + (size_t)row * S_LEN);
    for (int v = threadIdx.x; v < end; v += 256) {
        float4 x = p[v];
        x.x *= linv; x.y *= linv; x.z *= linv; x.w *= linv;
        p[v] = x;
    }
}

// =================================================================
extern "C" void kernel_launch(void* const* d_in, const int* in_sizes, int n_in,
                              void* d_out, int out_size)
{
    const float* X   = (const float*)d_in[0];
    const float* WQ  = (const float*)d_in[1];
    const float* WK  = (const float*)d_in[2];
    const float* WV  = (const float*)d_in[3];
    const float* WOw = (const float*)d_in[4];
    const float* WOb = (const float*)d_in[5];
    const float* F1w = (const float*)d_in[6];
    const float* F1b = (const float*)d_in[7];
    const float* F2w = (const float*)d_in[8];
    const float* F2b = (const float*)d_in[9];

    float *Ap, *Lp, *Dp;
    uint32_t *Xh2, *Xl2, *WQh2, *WQl2, *WKh2, *WKl2, *Qh2, *Ql2, *Kh2, *Kl2;
    uint32_t *Xf2, *WVf2, *WOf2, *F1f2, *F2f2, *Vf2, *Zf2, *ATTf2, *HIDf2;
    cudaGetSymbolAddress((void**)&Ap, g_ATT);
    cudaGetSymbolAddress((void**)&Lp, g_L);
    cudaGetSymbolAddress((void**)&Dp, g_DUMMY);
    cudaGetSymbolAddress((void**)&Xh2, g_Xh2);
    cudaGetSymbolAddress((void**)&Xl2, g_Xl2);
    cudaGetSymbolAddress((void**)&WQh2, g_WQh2);
    cudaGetSymbolAddress((void**)&WQl2, g_WQl2);
    cudaGetSymbolAddress((void**)&WKh2, g_WKh2);
    cudaGetSymbolAddress((void**)&WKl2, g_WKl2);
    cudaGetSymbolAddress((void**)&Qh2, g_Qh2);
    cudaGetSymbolAddress((void**)&Ql2, g_Ql2);
    cudaGetSymbolAddress((void**)&Kh2, g_Kh2);
    cudaGetSymbolAddress((void**)&Kl2, g_Kl2);
    cudaGetSymbolAddress((void**)&Xf2, g_Xf2);
    cudaGetSymbolAddress((void**)&WVf2, g_WVf2);
    cudaGetSymbolAddress((void**)&WOf2, g_WOf2);
    cudaGetSymbolAddress((void**)&F1f2, g_F1f2);
    cudaGetSymbolAddress((void**)&F2f2, g_F2f2);
    cudaGetSymbolAddress((void**)&Vf2, g_Vf2);
    cudaGetSymbolAddress((void**)&Zf2, g_Zf2);
    cudaGetSymbolAddress((void**)&ATTf2, g_ATTf2);
    cudaGetSymbolAddress((void**)&HIDf2, g_HIDf2);

    const size_t SA_EL = (size_t)N_HEADS * S_LEN * S_LEN;
    const size_t OV_EL = (size_t)S_LEN * D_MODEL;
    float* out = (float*)d_out;
    float* sa;
    float* ov;
    if ((size_t)out_size >= SA_EL + OV_EL)      { sa = out;     ov = out + SA_EL; }
    else if ((size_t)out_size >= SA_EL)         { sa = out;     ov = Dp; }
    else                                        { sa = nullptr; ov = out; }

    const int attn_smem  = ATTN_SMEM_U32 * 4;             // 73728 (x3 CTAs = 221184)
    const int qk_smem    = 8 * QSTG * 4;
    const int f16_smem   = 3 * (128 * FP + 128 * FP) * 4;
    const int f16_smem64 = 3 * (64 * FP + 128 * FP) * 4;
    cudaFuncSetAttribute(attn_tc, cudaFuncAttributeMaxDynamicSharedMemorySize, attn_smem);
    cudaFuncSetAttribute(gemm_qk, cudaFuncAttributeMaxDynamicSharedMemorySize, qk_smem);
    cudaFuncSetAttribute(gemm_f16<128,false,false,false,false,false,true >,
                         cudaFuncAttributeMaxDynamicSharedMemorySize, f16_smem);
    cudaFuncSetAttribute(gemm_f16<64 ,true ,false,true ,true ,true ,false>,
                         cudaFuncAttributeMaxDynamicSharedMemorySize, f16_smem64);
    cudaFuncSetAttribute(gemm_f16<128,true ,true ,false,false,true ,false>,
                         cudaFuncAttributeMaxDynamicSharedMemorySize, f16_smem);
    cudaFuncSetAttribute(gemm_f16<64 ,true ,false,true ,true ,false,false>,
                         cudaFuncAttributeMaxDynamicSharedMemorySize, f16_smem64);

    static cudaStream_t s2 = nullptr;
    static cudaEvent_t evStart = nullptr, evX = nullptr, evV = nullptr,
                       evAttn = nullptr, evSide = nullptr, evPack = nullptr;
    if (!s2) {
        cudaStreamCreateWithFlags(&s2, cudaStreamNonBlocking);
        cudaEventCreateWithFlags(&evStart, cudaEventDisableTiming);
        cudaEventCreateWithFlags(&evX,     cudaEventDisableTiming);
        cudaEventCreateWithFlags(&evV,     cudaEventDisableTiming);
        cudaEventCreateWithFlags(&evAttn,  cudaEventDisableTiming);
        cudaEventCreateWithFlags(&evSide,  cudaEventDisableTiming);
        cudaEventCreateWithFlags(&evPack,  cudaEventDisableTiming);
    }

    dim3 blk(256);

    // ---- fork side stream ----
    cudaEventRecord(evStart, 0);
    cudaStreamWaitEvent(s2, evStart, 0);

    // ---- main: pack X ----
    pack_x<<<dim3(2048), blk>>>(X, Xh2, Xl2, Xf2, S_LEN * D_MODEL / 4);
    cudaEventRecord(evX, 0);

    // ---- s2: WV pack -> V-GEMM, then SA zero + late-weight packs ----
    pack_wf_head<<<dim3(2048), blk, 0, s2>>>(WV, WVf2);
    cudaStreamWaitEvent(s2, evX, 0);
    gemm_f16<128,false,false,false,false,false,true ><<<dim3(8, 16), blk, f16_smem, s2>>>(
        Xf2, WVf2, nullptr, nullptr, nullptr, Vf2, S_LEN, D_MODEL, D_MODEL);
    cudaEventRecord(evV, s2);
    if (sa)
        sa_zero<<<dim3(N_HEADS * S_LEN), blk, 0, s2>>>(sa);
    pack_wf_row<<<dim3(2048), blk, 0, s2>>>(WOw, WOf2, D_MODEL * D_MODEL / 2);
    pack_wf_row<<<dim3(8192), blk, 0, s2>>>(F1w, F1f2, D_FF * D_MODEL / 2);
    pack_wf_row<<<dim3(8192), blk, 0, s2>>>(F2w, F2f2, D_MODEL * D_FF / 2);
    cudaEventRecord(evPack, s2);

    // ---- main: merged QK pack + QK projection ----
    pack_w2<<<dim3(2048, 2), blk>>>(WQ, WK, WQh2, WQl2, WKh2, WKl2);
    gemm_qk<<<dim3(8, 16, 2), blk, qk_smem>>>(Xh2, Xl2,
        WQh2, WQl2, WKh2, WKl2, Qh2, Ql2, Kh2, Kl2);

    cudaStreamWaitEvent(0, evV, 0);
    attn_tc<<<dim3(S_LEN / 64, N_HEADS), blk, attn_smem>>>(
        Qh2, Ql2, Kh2, Kl2, Vf2, sa, Zf2, Lp);

    // ---- fork: rescale SA overlapping WO/FF ----
    cudaEventRecord(evAttn, 0);
    if (sa) {
        cudaStreamWaitEvent(s2, evAttn, 0);
        sa_rescale<<<dim3(N_HEADS * S_LEN), blk, 0, s2>>>(sa, Lp);
        cudaEventRecord(evSide, s2);
    }

    cudaStreamWaitEvent(0, evPack, 0);

    // ATT = X + Z @ WO^T + b   (MT=64, grid 256)
    gemm_f16<64 ,true ,false,true ,true ,true ,false><<<dim3(8, 32), blk, f16_smem64>>>(
        Zf2, WOf2, WOb, X, Ap, ATTf2, S_LEN, D_MODEL, D_MODEL);
    // HID = relu(ATT @ FF1^T + b1)   (MT=128, grid 512)
    gemm_f16<128,true ,true ,false,false,true ,false><<<dim3(32, 16), blk, f16_smem>>>(
        ATTf2, F1f2, F1b, nullptr, nullptr, HIDf2, S_LEN, D_FF, D_MODEL);
    // out = ATT + HID @ FF2^T + b2   (MT=64, grid 256)
    gemm_f16<64 ,true ,false,true ,true ,false,false><<<dim3(8, 32), blk, f16_smem64>>>(
        HIDf2, F2f2, F2b, Ap, ov, nullptr, S_LEN, D_MODEL, D_FF);

    if (sa)
        cudaStreamWaitEvent(0, evSide, 0);
}